// round 7
// baseline (speedup 1.0000x reference)
#include <cuda_runtime.h>
#include <float.h>
#include <math.h>

// ---------------- problem constants ----------------
#define NMAX   16000
#define NGRAPH 16
#define NPG    1000          // nodes per graph
#define KNN    20
#define HDIM   64
#define LAYERS 4

// ---------------- device scratch (no allocations allowed) ----------------
__device__ float g_hbuf[2][NMAX * HDIM];   // ping-pong node features (fp32)
__device__ float g_s64[NMAX * HDIM];       // prefix chain: x_i over W rows 0..63 (NO bias)
__device__ float g_sq[NMAX];               // ||h_i||^2, scalar-serial (XLA-CPU order)
__device__ int   g_knn[NMAX * KNN];        // global neighbor indices
__device__ float g_d2[NGRAPH * NPG * NPG]; // per-graph distance matrices (64MB)

__device__ __forceinline__ float eluf(float x) {
    return x > 0.0f ? x : expm1f(x);
}

// ---------------- lc_encode: x[N,8] -> h[N,64] ----------------
// Eigen GEMM = serial ascending single-accumulator FMA chain; bias added after; elu.
__global__ void lc_kernel(const float* __restrict__ x,
                          const float* __restrict__ W1, const float* __restrict__ b1,
                          const float* __restrict__ W2, const float* __restrict__ b2) {
    int i = blockIdx.x;
    int tid = threadIdx.x;           // 64 threads
    __shared__ float xs[8];
    __shared__ float h1[32];
    if (tid < 8) xs[tid] = x[i * 8 + tid];
    __syncthreads();
    if (tid < 32) {
        float s = 0.0f;
#pragma unroll
        for (int e = 0; e < 8; e++) s = __fmaf_rn(xs[e], W1[e * 32 + tid], s);
        h1[tid] = eluf(__fadd_rn(s, b1[tid]));
    }
    __syncthreads();
    float s = 0.0f;
#pragma unroll
    for (int e = 0; e < 32; e++) s = __fmaf_rn(h1[e], W2[e * 64 + tid], s);
    g_hbuf[0][i * 64 + tid] = eluf(__fadd_rn(s, b2[tid]));
}

// ---------------- sq: XLA-CPU scalar reduce emulation ----------------
// acc = 0; for k ascending: acc = add(acc, mul(x,x)). No fma, no tree.
__global__ void sq_kernel(int src) {
    int node = blockIdx.x * 128 + threadIdx.x;
    const float* h = g_hbuf[src] + node * 64;
    float acc = 0.0f;
#pragma unroll 8
    for (int k = 0; k < 64; k++)
        acc = __fadd_rn(acc, __fmul_rn(h[k], h[k]));
    g_sq[node] = acc;
}

// ---------------- s64 prefix: serial chain of x_i over W rows 0..63 (NO bias) ----------------
// block = 256 threads = 4 nodes x 64 channels
__global__ void ac_kernel(int src, const float* __restrict__ convW, int l) {
    int tid = threadIdx.x;
    int nl = tid >> 6, d = tid & 63;
    int i = blockIdx.x * 4 + nl;
    const float* Hh = g_hbuf[src];
    __shared__ float hs[4][64];
    hs[nl][d] = Hh[i * 64 + d];
    __syncthreads();
    const float* W = convW + l * 128 * 64;
    float a = 0.0f;
#pragma unroll 8
    for (int e = 0; e < 64; e++)
        a = __fmaf_rn(hs[nl][e], W[e * 64 + d], a);
    g_s64[i * 64 + d] = a;
}

// ---------------- pairwise distance: d2 = sub(add(sq_i,sq_j), mul(2,dot)) ----------------
// dot = serial ascending fp32 FMA chain (Eigen/cublas structure). Uncontracted epilogue.
#define TM 128
#define KC 32
#define NTILE 8                              // ceil(NPG/TM)
#define NPAIRS (NTILE * (NTILE + 1) / 2)     // 36
__global__ void dist_kernel(int src) {
    const float* Hh = g_hbuf[src];
    int g = blockIdx.z;
    int idx = blockIdx.x;
    int ti = (int)((sqrtf(8.0f * (float)idx + 1.0f) - 1.0f) * 0.5f);
    while ((ti + 1) * (ti + 2) / 2 <= idx) ti++;
    while (ti * (ti + 1) / 2 > idx) ti--;
    int tj = idx - ti * (ti + 1) / 2;

    int i0 = ti * TM;
    int j0 = tj * TM;
    int base = g * NPG;
    __shared__ __align__(16) float His[KC][TM + 4];
    __shared__ __align__(16) float Hjs[KC][TM + 4];
    int tid = threadIdx.x;           // 256 threads
    int tx = tid & 15, ty = tid >> 4;
    float acc[8][8];
#pragma unroll
    for (int a = 0; a < 8; a++)
#pragma unroll
        for (int b = 0; b < 8; b++) acc[a][b] = 0.0f;

    for (int kc = 0; kc < HDIM; kc += KC) {
        __syncthreads();
        for (int t = tid; t < TM * KC; t += 256) {
            int node = t >> 5;
            int k = t & 31;
            int gi = i0 + node;
            His[k][node] = (gi < NPG) ? Hh[(base + gi) * 64 + kc + k] : 0.0f;
            int gj = j0 + node;
            Hjs[k][node] = (gj < NPG) ? Hh[(base + gj) * 64 + kc + k] : 0.0f;
        }
        __syncthreads();
#pragma unroll
        for (int k = 0; k < KC; k++) {
            float av[8], bv[8];
            *(float4*)&av[0] = *(const float4*)&His[k][ty * 8];
            *(float4*)&av[4] = *(const float4*)&His[k][ty * 8 + 4];
            *(float4*)&bv[0] = *(const float4*)&Hjs[k][tx * 8];
            *(float4*)&bv[4] = *(const float4*)&Hjs[k][tx * 8 + 4];
#pragma unroll
            for (int a = 0; a < 8; a++)
#pragma unroll
                for (int b = 0; b < 8; b++)
                    acc[a][b] = __fmaf_rn(av[a], bv[b], acc[a][b]);
        }
    }
    float* d2g = g_d2 + (size_t)g * NPG * NPG;
#pragma unroll
    for (int a = 0; a < 8; a++) {
        int gi = i0 + ty * 8 + a;
        if (gi >= NPG) continue;
        float si = g_sq[base + gi];
#pragma unroll
        for (int b = 0; b < 8; b++) {
            int gj = j0 + tx * 8 + b;
            if (gj >= NPG) continue;
            float sj = g_sq[base + gj];
            float v = __fsub_rn(__fadd_rn(si, sj), __fmul_rn(2.0f, acc[a][b]));
            d2g[gi * NPG + gj] = v;
            if (ti != tj) d2g[gj * NPG + gi] = v;
        }
    }
}

// ---------------- top-K selection (argmin x20, tie-break lower index) ----------------
__device__ __forceinline__ void argmin2(float& v, int& i, float v2, int i2) {
    if (v2 < v || (v2 == v && i2 < i)) { v = v2; i = i2; }
}

__global__ void knn_kernel() {
    int i = blockIdx.x;
    int g = i / NPG;
    int il = i % NPG;
    int tid = threadIdx.x;           // 256 threads
    __shared__ float sd[NPG];
    __shared__ float rv[8];
    __shared__ int   ri[8];
    const float* row = g_d2 + (size_t)g * NPG * NPG + (size_t)il * NPG;
    for (int j = tid; j < NPG; j += 256) sd[j] = row[j];
    __syncthreads();

    int lane = tid & 31, wid = tid >> 5;
    for (int it = 0; it < KNN; it++) {
        float bv = FLT_MAX;
        int bi = 1 << 30;
        for (int j = tid; j < NPG; j += 256) {
            float v = sd[j];
            if (v < bv || (v == bv && j < bi)) { bv = v; bi = j; }
        }
#pragma unroll
        for (int off = 16; off > 0; off >>= 1) {
            float v2 = __shfl_down_sync(0xFFFFFFFFu, bv, off);
            int   i2 = __shfl_down_sync(0xFFFFFFFFu, bi, off);
            argmin2(bv, bi, v2, i2);
        }
        if (lane == 0) { rv[wid] = bv; ri[wid] = bi; }
        __syncthreads();
        if (tid < 32) {
            bv = (tid < 8) ? rv[tid] : FLT_MAX;
            bi = (tid < 8) ? ri[tid] : (1 << 30);
#pragma unroll
            for (int off = 16; off > 0; off >>= 1) {
                float v2 = __shfl_down_sync(0xFFFFFFFFu, bv, off);
                int   i2 = __shfl_down_sync(0xFFFFFFFFu, bi, off);
                argmin2(bv, bi, v2, i2);
            }
            if (tid == 0) {
                g_knn[i * KNN + it] = g * NPG + bi;
                sd[bi] = FLT_MAX;
            }
        }
        __syncthreads();
    }
}

// ---------------- edge MLP + BN + max aggregation + residual ----------------
// msg_d = elu( (128-term serial chain: s64 prefix + diff_k*W[64+k][d], k ascending) + bias_d )
// BN: ((g*(e-m)) * (1/sqrt(v+eps))) + be  — exact reference association, precise div/sqrt.
// block = 128 threads = 4 warps, one node per warp; lane owns channels (lane, lane+32).
__global__ void agg_kernel(int src, const float* __restrict__ convW,
                           const float* __restrict__ convb,
                           const float* __restrict__ bn_g, const float* __restrict__ bn_b,
                           const float* __restrict__ bn_m, const float* __restrict__ bn_v,
                           int l) {
    __shared__ float Wb[64][64];           // bottom half of W (rows 64..127)
    __shared__ float diff[4][KNN][64];     // xj - xi
    __shared__ int   idxs[4][KNN];

    int tid = threadIdx.x;
    int nl = tid >> 5, lane = tid & 31;
    int i = blockIdx.x * 4 + nl;
    const float* Hh = g_hbuf[src];
    float* hdst = g_hbuf[src ^ 1];
    const float* W = convW + l * 128 * 64;

    for (int t = tid; t < 4096; t += 128) {
        int e = t >> 6, d = t & 63;
        Wb[e][d] = W[(64 + e) * 64 + d];
    }
    if (lane < KNN) idxs[nl][lane] = g_knn[i * KNN + lane];
    __syncthreads();

    float xi0 = Hh[i * 64 + lane];
    float xi1 = Hh[i * 64 + lane + 32];

#pragma unroll
    for (int nb = 0; nb < KNN; nb++) {
        const float* hj = Hh + idxs[nl][nb] * 64;
        diff[nl][nb][lane]      = __fsub_rn(hj[lane],      xi0);
        diff[nl][nb][lane + 32] = __fsub_rn(hj[lane + 32], xi1);
    }
    __syncwarp();

    float s0 = g_s64[i * 64 + lane];
    float s1 = g_s64[i * 64 + lane + 32];
    float acc0[KNN], acc1[KNN];
#pragma unroll
    for (int nb = 0; nb < KNN; nb++) { acc0[nb] = s0; acc1[nb] = s1; }

#pragma unroll 4
    for (int k = 0; k < 64; k++) {
        float w0 = Wb[k][lane];
        float w1 = Wb[k][lane + 32];
#pragma unroll
        for (int nb = 0; nb < KNN; nb++) {
            float dk = diff[nl][nb][k];
            acc0[nb] = __fmaf_rn(dk, w0, acc0[nb]);
            acc1[nb] = __fmaf_rn(dk, w1, acc1[nb]);
        }
    }

    float bi0 = convb[l * 64 + lane],  bi1 = convb[l * 64 + lane + 32];
    float mm0 = bn_m[l * 64 + lane],   mm1 = bn_m[l * 64 + lane + 32];
    float bb0 = bn_b[l * 64 + lane],   bb1 = bn_b[l * 64 + lane + 32];
    float gg0 = bn_g[l * 64 + lane],   gg1 = bn_g[l * 64 + lane + 32];
    // CPU rsqrt = exact 1/sqrt (correctly rounded), NOT the GPU approx
    float rr0 = __fdiv_rn(1.0f, __fsqrt_rn(__fadd_rn(bn_v[l * 64 + lane],      1e-5f)));
    float rr1 = __fdiv_rn(1.0f, __fsqrt_rn(__fadd_rn(bn_v[l * 64 + lane + 32], 1e-5f)));
    float best0 = -FLT_MAX, best1 = -FLT_MAX;
#pragma unroll
    for (int nb = 0; nb < KNN; nb++) {
        float e0 = eluf(__fadd_rn(acc0[nb], bi0));
        float e1 = eluf(__fadd_rn(acc1[nb], bi1));
        float v0 = __fadd_rn(__fmul_rn(__fmul_rn(gg0, __fsub_rn(e0, mm0)), rr0), bb0);
        float v1 = __fadd_rn(__fmul_rn(__fmul_rn(gg1, __fsub_rn(e1, mm1)), rr1), bb1);
        best0 = fmaxf(best0, v0);
        best1 = fmaxf(best1, v1);
    }
    hdst[i * 64 + lane]      = __fadd_rn(best0, xi0);
    hdst[i * 64 + lane + 32] = __fadd_rn(best1, xi1);
}

// ---------------- output heads (serial chains, bias after) ----------------
__global__ void heads_kernel(int src,
                             const float* __restrict__ oW1, const float* __restrict__ ob1,
                             const float* __restrict__ oW2, const float* __restrict__ ob2,
                             const float* __restrict__ oW3, const float* __restrict__ ob3,
                             const float* __restrict__ sW1, const float* __restrict__ sb1,
                             const float* __restrict__ sW2, const float* __restrict__ sb2,
                             const float* __restrict__ sW3, const float* __restrict__ sb3,
                             float* __restrict__ out, int out_size, int N) {
    int i = blockIdx.x;
    int tid = threadIdx.x;           // 64 threads
    const float* Hh = g_hbuf[src];
    __shared__ float hr[64];
    __shared__ float t1[64];
    __shared__ float t2[32];
    hr[tid] = Hh[i * 64 + tid];
    __syncthreads();

    // ---- out head ----
    float s = 0.0f;
#pragma unroll 8
    for (int e = 0; e < 64; e++) s = __fmaf_rn(hr[e], oW1[e * 64 + tid], s);
    t1[tid] = eluf(__fadd_rn(s, ob1[tid]));
    __syncthreads();
    if (tid < 32) {
        float s2 = 0.0f;
#pragma unroll 8
        for (int e = 0; e < 64; e++) s2 = __fmaf_rn(t1[e], oW2[e * 32 + tid], s2);
        t2[tid] = eluf(__fadd_rn(s2, ob2[tid]));
    }
    __syncthreads();
    if (tid < 8) {
        float s3 = 0.0f;
#pragma unroll
        for (int e = 0; e < 32; e++) s3 = __fmaf_rn(t2[e], oW3[e * 8 + tid], s3);
        out[i * 8 + tid] = __fadd_rn(s3, ob3[tid]);
    }
    __syncthreads();

    // ---- split head ----
    s = 0.0f;
#pragma unroll 8
    for (int e = 0; e < 64; e++) s = __fmaf_rn(hr[e], sW1[e * 64 + tid], s);
    t1[tid] = eluf(__fadd_rn(s, sb1[tid]));
    __syncthreads();
    if (tid < 32) {
        float s2 = 0.0f;
#pragma unroll 8
        for (int e = 0; e < 64; e++) s2 = __fmaf_rn(t1[e], sW2[e * 32 + tid], s2);
        t2[tid] = eluf(__fadd_rn(s2, sb2[tid]));
    }
    __syncthreads();
    if (tid == 0) {
        float s3 = 0.0f;
#pragma unroll
        for (int e = 0; e < 32; e++) s3 = __fmaf_rn(t2[e], sW3[e], s3);
        s3 = __fadd_rn(s3, sb3[0]);
        int off_sp = N * 8;
        if (off_sp + i < out_size) out[off_sp + i] = s3;
        int off_b = N * 9;
        if (off_b + i < out_size) out[off_b + i] = (float)(i / NPG);
    }
}

// ---------------- host launcher ----------------
extern "C" void kernel_launch(void* const* d_in, const int* in_sizes, int n_in,
                              void* d_out, int out_size) {
    const float* x     = (const float*)d_in[0];
    // d_in[1] = batch (recomputed analytically)
    const float* lcW1  = (const float*)d_in[2];
    const float* lcb1  = (const float*)d_in[3];
    const float* lcW2  = (const float*)d_in[4];
    const float* lcb2  = (const float*)d_in[5];
    const float* convW = (const float*)d_in[6];
    const float* convb = (const float*)d_in[7];
    const float* bn_g  = (const float*)d_in[8];
    const float* bn_b  = (const float*)d_in[9];
    const float* bn_m  = (const float*)d_in[10];
    const float* bn_v  = (const float*)d_in[11];
    const float* outW1 = (const float*)d_in[12];
    const float* outb1 = (const float*)d_in[13];
    const float* outW2 = (const float*)d_in[14];
    const float* outb2 = (const float*)d_in[15];
    const float* outW3 = (const float*)d_in[16];
    const float* outb3 = (const float*)d_in[17];
    const float* spW1  = (const float*)d_in[18];
    const float* spb1  = (const float*)d_in[19];
    const float* spW2  = (const float*)d_in[20];
    const float* spb2  = (const float*)d_in[21];
    const float* spW3  = (const float*)d_in[22];
    const float* spb3  = (const float*)d_in[23];

    const int N = in_sizes[0] / 8;          // 16000

    lc_kernel<<<N, 64>>>(x, lcW1, lcb1, lcW2, lcb2);

    int src = 0;
    for (int l = 0; l < LAYERS; l++) {
        sq_kernel<<<N / 128, 128>>>(src);
        ac_kernel<<<N / 4, 256>>>(src, convW, l);
        dist_kernel<<<dim3(NPAIRS, 1, NGRAPH), 256>>>(src);
        knn_kernel<<<N, 256>>>();
        agg_kernel<<<N / 4, 128>>>(src, convW, convb, bn_g, bn_b, bn_m, bn_v, l);
        src ^= 1;
    }

    heads_kernel<<<N, 64>>>(src, outW1, outb1, outW2, outb2, outW3, outb3,
                            spW1, spb1, spW2, spb2, spW3, spb3,
                            (float*)d_out, out_size, N);
}

// round 8
// speedup vs baseline: 1.4453x; 1.4453x over previous
#include <cuda_runtime.h>
#include <float.h>
#include <math.h>

// ---------------- problem constants ----------------
#define NMAX   16000
#define NGRAPH 16
#define NPG    1000          // nodes per graph
#define KNN    20
#define HDIM   64
#define LAYERS 4

// ---------------- device scratch (no allocations allowed) ----------------
__device__ float g_hbuf[2][NMAX * HDIM];   // ping-pong node features (fp32)
__device__ float g_s64[NMAX * HDIM];       // prefix chain: x_i over W rows 0..63 (NO bias)
__device__ float g_sq[NMAX];               // ||h_i||^2, scalar-serial (XLA-CPU order)
__device__ int   g_knn[NMAX * KNN];        // global neighbor indices
__device__ float g_d2[NGRAPH * NPG * NPG]; // per-graph distance matrices (64MB)

__device__ __forceinline__ float eluf(float x) {
    return x > 0.0f ? x : expm1f(x);
}

// ---------------- lc_encode: x[N,8] -> h[N,64], 32 nodes/block, weights in smem ----------------
// Per-output serial ascending FMA chain, bias after — bitwise identical to prior version.
__global__ void lc_kernel(const float* __restrict__ x,
                          const float* __restrict__ W1, const float* __restrict__ b1,
                          const float* __restrict__ W2, const float* __restrict__ b2) {
    __shared__ float sW1[8 * 32], sW2[32 * 64];
    __shared__ float sb1[32], sb2[64];
    __shared__ float sx[32][9];
    __shared__ float sh1[32][33];
    int tid = threadIdx.x;                 // 256
    int i0 = blockIdx.x * 32;

    sW1[tid] = W1[tid];                    // 256 = 8*32
    for (int t = tid; t < 32 * 64; t += 256) sW2[t] = W2[t];
    if (tid < 32) sb1[tid] = b1[tid];
    if (tid < 64) sb2[tid] = b2[tid];
    sx[tid >> 3][tid & 7] = x[(i0 + (tid >> 3)) * 8 + (tid & 7)];
    __syncthreads();

    int node = tid >> 3, slot = tid & 7;
    // stage 1: 32 outputs per node, 4 per thread
#pragma unroll
    for (int oo = 0; oo < 4; oo++) {
        int o = slot * 4 + oo;
        float s = 0.0f;
#pragma unroll
        for (int e = 0; e < 8; e++) s = __fmaf_rn(sx[node][e], sW1[e * 32 + o], s);
        sh1[node][o] = eluf(__fadd_rn(s, sb1[o]));
    }
    __syncthreads();
    // stage 2: 64 outputs per node, 8 per thread
#pragma unroll
    for (int oo = 0; oo < 8; oo++) {
        int o = slot * 8 + oo;
        float s = 0.0f;
#pragma unroll
        for (int e = 0; e < 32; e++) s = __fmaf_rn(sh1[node][e], sW2[e * 64 + o], s);
        g_hbuf[0][(i0 + node) * 64 + o] = eluf(__fadd_rn(s, sb2[o]));
    }
}

// ---------------- sq: scalar-serial chain (XLA-CPU order), smem-staged for coalescing ----------------
__global__ void sq_kernel(int src) {
    __shared__ float sh[128][65];          // pad 65 -> conflict-free row walk
    int tid = threadIdx.x;                 // 128
    int i0 = blockIdx.x * 128;
    const float* H = g_hbuf[src] + i0 * 64;
    for (int t = tid; t < 128 * 64; t += 128)
        sh[t >> 6][t & 63] = H[t];
    __syncthreads();
    float acc = 0.0f;
#pragma unroll 8
    for (int k = 0; k < 64; k++) {
        float v = sh[tid][k];
        acc = __fadd_rn(acc, __fmul_rn(v, v));
    }
    g_sq[i0 + tid] = acc;
}

// ---------------- s64 prefix: serial chain of x_i over W rows 0..63 (NO bias) ----------------
__global__ void ac_kernel(int src, const float* __restrict__ convW, int l) {
    int tid = threadIdx.x;
    int nl = tid >> 6, d = tid & 63;
    int i = blockIdx.x * 4 + nl;
    const float* Hh = g_hbuf[src];
    __shared__ float hs[4][64];
    hs[nl][d] = Hh[i * 64 + d];
    __syncthreads();
    const float* W = convW + l * 128 * 64;
    float a = 0.0f;
#pragma unroll 8
    for (int e = 0; e < 64; e++)
        a = __fmaf_rn(hs[nl][e], W[e * 64 + d], a);
    g_s64[i * 64 + d] = a;
}

// ---------------- pairwise distance: d2 = sub(add(sq_i,sq_j), mul(2,dot)) ----------------
// UNCHANGED (numerics-critical, passing config)
#define TM 128
#define KC 32
#define NTILE 8
#define NPAIRS (NTILE * (NTILE + 1) / 2)     // 36
__global__ void dist_kernel(int src) {
    const float* Hh = g_hbuf[src];
    int g = blockIdx.z;
    int idx = blockIdx.x;
    int ti = (int)((sqrtf(8.0f * (float)idx + 1.0f) - 1.0f) * 0.5f);
    while ((ti + 1) * (ti + 2) / 2 <= idx) ti++;
    while (ti * (ti + 1) / 2 > idx) ti--;
    int tj = idx - ti * (ti + 1) / 2;

    int i0 = ti * TM;
    int j0 = tj * TM;
    int base = g * NPG;
    __shared__ __align__(16) float His[KC][TM + 4];
    __shared__ __align__(16) float Hjs[KC][TM + 4];
    int tid = threadIdx.x;           // 256 threads
    int tx = tid & 15, ty = tid >> 4;
    float acc[8][8];
#pragma unroll
    for (int a = 0; a < 8; a++)
#pragma unroll
        for (int b = 0; b < 8; b++) acc[a][b] = 0.0f;

    for (int kc = 0; kc < HDIM; kc += KC) {
        __syncthreads();
        for (int t = tid; t < TM * KC; t += 256) {
            int node = t >> 5;
            int k = t & 31;
            int gi = i0 + node;
            His[k][node] = (gi < NPG) ? Hh[(base + gi) * 64 + kc + k] : 0.0f;
            int gj = j0 + node;
            Hjs[k][node] = (gj < NPG) ? Hh[(base + gj) * 64 + kc + k] : 0.0f;
        }
        __syncthreads();
#pragma unroll
        for (int k = 0; k < KC; k++) {
            float av[8], bv[8];
            *(float4*)&av[0] = *(const float4*)&His[k][ty * 8];
            *(float4*)&av[4] = *(const float4*)&His[k][ty * 8 + 4];
            *(float4*)&bv[0] = *(const float4*)&Hjs[k][tx * 8];
            *(float4*)&bv[4] = *(const float4*)&Hjs[k][tx * 8 + 4];
#pragma unroll
            for (int a = 0; a < 8; a++)
#pragma unroll
                for (int b = 0; b < 8; b++)
                    acc[a][b] = __fmaf_rn(av[a], bv[b], acc[a][b]);
        }
    }
    float* d2g = g_d2 + (size_t)g * NPG * NPG;
#pragma unroll
    for (int a = 0; a < 8; a++) {
        int gi = i0 + ty * 8 + a;
        if (gi >= NPG) continue;
        float si = g_sq[base + gi];
#pragma unroll
        for (int b = 0; b < 8; b++) {
            int gj = j0 + tx * 8 + b;
            if (gj >= NPG) continue;
            float sj = g_sq[base + gj];
            float v = __fsub_rn(__fadd_rn(si, sj), __fmul_rn(2.0f, acc[a][b]));
            d2g[gi * NPG + gj] = v;
            if (ti != tj) d2g[gj * NPG + gi] = v;
        }
    }
}

// ---------------- top-K selection: warp-per-row, register-resident, no barriers ----------------
// Selection semantics identical: 20x argmin with lexicographic (value, index) tie-break.
__global__ void knn_kernel() {
    int i = blockIdx.x * 8 + (threadIdx.x >> 5);   // node = global warp id
    int lane = threadIdx.x & 31;
    int g = i / NPG;
    int il = i % NPG;
    const float* row = g_d2 + (size_t)g * NPG * NPG + (size_t)il * NPG;

    float v[32];
#pragma unroll
    for (int c = 0; c < 32; c++) {
        int j = lane + 32 * c;
        v[c] = (j < NPG) ? row[j] : FLT_MAX;
    }
    unsigned used = 0;
    for (int it = 0; it < KNN; it++) {
        // local argmin over non-used (ascending c -> lowest index kept on ties via strict <)
        float bv = FLT_MAX;
        int bc = 32;
#pragma unroll
        for (int c = 0; c < 32; c++) {
            if (!((used >> c) & 1u) && v[c] < bv) { bv = v[c]; bc = c; }
        }
        int bj = (bc < 32) ? (lane + 32 * bc) : (1 << 30);
        // warp argmin, lexicographic (v, j)
        float rv = bv; int rj = bj;
#pragma unroll
        for (int off = 16; off > 0; off >>= 1) {
            float ov = __shfl_down_sync(0xFFFFFFFFu, rv, off);
            int   oj = __shfl_down_sync(0xFFFFFFFFu, rj, off);
            if (ov < rv || (ov == rv && oj < rj)) { rv = ov; rj = oj; }
        }
        rj = __shfl_sync(0xFFFFFFFFu, rj, 0);
        if (lane == (rj & 31)) used |= 1u << (rj >> 5);
        if (lane == 0) g_knn[i * KNN + it] = g * NPG + rj;
    }
}

// ---------------- edge MLP + BN + max aggregation + residual ----------------
// UNCHANGED numerics (passing config): 128-term serial chain continuation, exact BN order.
__global__ void agg_kernel(int src, const float* __restrict__ convW,
                           const float* __restrict__ convb,
                           const float* __restrict__ bn_g, const float* __restrict__ bn_b,
                           const float* __restrict__ bn_m, const float* __restrict__ bn_v,
                           int l) {
    __shared__ float Wb[64][64];
    __shared__ float diff[4][KNN][64];
    __shared__ int   idxs[4][KNN];

    int tid = threadIdx.x;
    int nl = tid >> 5, lane = tid & 31;
    int i = blockIdx.x * 4 + nl;
    const float* Hh = g_hbuf[src];
    float* hdst = g_hbuf[src ^ 1];
    const float* W = convW + l * 128 * 64;

    for (int t = tid; t < 4096; t += 128) {
        int e = t >> 6, d = t & 63;
        Wb[e][d] = W[(64 + e) * 64 + d];
    }
    if (lane < KNN) idxs[nl][lane] = g_knn[i * KNN + lane];
    __syncthreads();

    float xi0 = Hh[i * 64 + lane];
    float xi1 = Hh[i * 64 + lane + 32];

#pragma unroll
    for (int nb = 0; nb < KNN; nb++) {
        const float* hj = Hh + idxs[nl][nb] * 64;
        diff[nl][nb][lane]      = __fsub_rn(hj[lane],      xi0);
        diff[nl][nb][lane + 32] = __fsub_rn(hj[lane + 32], xi1);
    }
    __syncwarp();

    float s0 = g_s64[i * 64 + lane];
    float s1 = g_s64[i * 64 + lane + 32];
    float acc0[KNN], acc1[KNN];
#pragma unroll
    for (int nb = 0; nb < KNN; nb++) { acc0[nb] = s0; acc1[nb] = s1; }

#pragma unroll 4
    for (int k = 0; k < 64; k++) {
        float w0 = Wb[k][lane];
        float w1 = Wb[k][lane + 32];
#pragma unroll
        for (int nb = 0; nb < KNN; nb++) {
            float dk = diff[nl][nb][k];
            acc0[nb] = __fmaf_rn(dk, w0, acc0[nb]);
            acc1[nb] = __fmaf_rn(dk, w1, acc1[nb]);
        }
    }

    float bi0 = convb[l * 64 + lane],  bi1 = convb[l * 64 + lane + 32];
    float mm0 = bn_m[l * 64 + lane],   mm1 = bn_m[l * 64 + lane + 32];
    float bb0 = bn_b[l * 64 + lane],   bb1 = bn_b[l * 64 + lane + 32];
    float gg0 = bn_g[l * 64 + lane],   gg1 = bn_g[l * 64 + lane + 32];
    float rr0 = __fdiv_rn(1.0f, __fsqrt_rn(__fadd_rn(bn_v[l * 64 + lane],      1e-5f)));
    float rr1 = __fdiv_rn(1.0f, __fsqrt_rn(__fadd_rn(bn_v[l * 64 + lane + 32], 1e-5f)));
    float best0 = -FLT_MAX, best1 = -FLT_MAX;
#pragma unroll
    for (int nb = 0; nb < KNN; nb++) {
        float e0 = eluf(__fadd_rn(acc0[nb], bi0));
        float e1 = eluf(__fadd_rn(acc1[nb], bi1));
        float v0 = __fadd_rn(__fmul_rn(__fmul_rn(gg0, __fsub_rn(e0, mm0)), rr0), bb0);
        float v1 = __fadd_rn(__fmul_rn(__fmul_rn(gg1, __fsub_rn(e1, mm1)), rr1), bb1);
        best0 = fmaxf(best0, v0);
        best1 = fmaxf(best1, v1);
    }
    hdst[i * 64 + lane]      = __fadd_rn(best0, xi0);
    hdst[i * 64 + lane + 32] = __fadd_rn(best1, xi1);
}

// ---------------- output heads: 32 nodes/block, weights staged in smem, heads sequential ----------------
// Per-output chains bitwise identical to prior version.
__global__ void heads_kernel(int src,
                             const float* __restrict__ oW1, const float* __restrict__ ob1,
                             const float* __restrict__ oW2, const float* __restrict__ ob2,
                             const float* __restrict__ oW3, const float* __restrict__ ob3,
                             const float* __restrict__ spW1, const float* __restrict__ spb1,
                             const float* __restrict__ spW2, const float* __restrict__ spb2,
                             const float* __restrict__ spW3, const float* __restrict__ spb3,
                             float* __restrict__ out, int out_size, int N) {
    __shared__ float sW1[64 * 64], sW2[64 * 32], sW3[32 * 8];
    __shared__ float sb1v[64], sb2v[32], sb3v[8];
    __shared__ float hr[32][65], t1[32][65], t2[32][33];
    int tid = threadIdx.x;               // 256
    int i0 = blockIdx.x * 32;
    const float* Hh = g_hbuf[src];

    for (int t = tid; t < 32 * 64; t += 256)
        hr[t >> 6][t & 63] = Hh[(i0 + (t >> 6)) * 64 + (t & 63)];

    int node = tid >> 3, slot = tid & 7;

    for (int head = 0; head < 2; head++) {
        const float* w1 = head == 0 ? oW1 : spW1;
        const float* w2 = head == 0 ? oW2 : spW2;
        const float* w3 = head == 0 ? oW3 : spW3;
        const float* c1 = head == 0 ? ob1 : spb1;
        const float* c2 = head == 0 ? ob2 : spb2;
        const float* c3 = head == 0 ? ob3 : spb3;
        int w3n = head == 0 ? 256 : 32;

        for (int t = tid; t < 4096; t += 256) sW1[t] = w1[t];
        for (int t = tid; t < 2048; t += 256) sW2[t] = w2[t];
        if (tid < 256 && tid < w3n) sW3[tid] = w3[tid];
        if (tid < 64) sb1v[tid] = c1[tid];
        if (tid < 32) sb2v[tid] = c2[tid];
        if (tid < 8)  sb3v[tid] = (head == 0) ? c3[tid] : (tid == 0 ? c3[0] : 0.0f);
        __syncthreads();

        // stage 1: 64 outputs/node, 8 per thread
#pragma unroll
        for (int oo = 0; oo < 8; oo++) {
            int o = slot * 8 + oo;
            float s = 0.0f;
#pragma unroll 8
            for (int e = 0; e < 64; e++) s = __fmaf_rn(hr[node][e], sW1[e * 64 + o], s);
            t1[node][o] = eluf(__fadd_rn(s, sb1v[o]));
        }
        __syncthreads();
        // stage 2: 32 outputs/node, 4 per thread
#pragma unroll
        for (int oo = 0; oo < 4; oo++) {
            int o = slot * 4 + oo;
            float s = 0.0f;
#pragma unroll 8
            for (int e = 0; e < 64; e++) s = __fmaf_rn(t1[node][e], sW2[e * 32 + o], s);
            t2[node][o] = eluf(__fadd_rn(s, sb2v[o]));
        }
        __syncthreads();
        // stage 3
        if (head == 0) {
            int o = slot;
            float s = 0.0f;
#pragma unroll
            for (int e = 0; e < 32; e++) s = __fmaf_rn(t2[node][e], sW3[e * 8 + o], s);
            out[(i0 + node) * 8 + o] = __fadd_rn(s, sb3v[o]);
        } else {
            if (slot == 0) {
                float s = 0.0f;
#pragma unroll
                for (int e = 0; e < 32; e++) s = __fmaf_rn(t2[node][e], sW3[e], s);
                s = __fadd_rn(s, sb3v[0]);
                int i = i0 + node;
                int off_sp = N * 8;
                if (off_sp + i < out_size) out[off_sp + i] = s;
                int off_b = N * 9;
                if (off_b + i < out_size) out[off_b + i] = (float)(i / NPG);
            }
        }
        __syncthreads();
    }
}

// ---------------- host launcher ----------------
extern "C" void kernel_launch(void* const* d_in, const int* in_sizes, int n_in,
                              void* d_out, int out_size) {
    const float* x     = (const float*)d_in[0];
    // d_in[1] = batch (recomputed analytically)
    const float* lcW1  = (const float*)d_in[2];
    const float* lcb1  = (const float*)d_in[3];
    const float* lcW2  = (const float*)d_in[4];
    const float* lcb2  = (const float*)d_in[5];
    const float* convW = (const float*)d_in[6];
    const float* convb = (const float*)d_in[7];
    const float* bn_g  = (const float*)d_in[8];
    const float* bn_b  = (const float*)d_in[9];
    const float* bn_m  = (const float*)d_in[10];
    const float* bn_v  = (const float*)d_in[11];
    const float* outW1 = (const float*)d_in[12];
    const float* outb1 = (const float*)d_in[13];
    const float* outW2 = (const float*)d_in[14];
    const float* outb2 = (const float*)d_in[15];
    const float* outW3 = (const float*)d_in[16];
    const float* outb3 = (const float*)d_in[17];
    const float* spW1  = (const float*)d_in[18];
    const float* spb1  = (const float*)d_in[19];
    const float* spW2  = (const float*)d_in[20];
    const float* spb2  = (const float*)d_in[21];
    const float* spW3  = (const float*)d_in[22];
    const float* spb3  = (const float*)d_in[23];

    const int N = in_sizes[0] / 8;          // 16000

    lc_kernel<<<N / 32, 256>>>(x, lcW1, lcb1, lcW2, lcb2);

    int src = 0;
    for (int l = 0; l < LAYERS; l++) {
        sq_kernel<<<N / 128, 128>>>(src);
        ac_kernel<<<N / 4, 256>>>(src, convW, l);
        dist_kernel<<<dim3(NPAIRS, 1, NGRAPH), 256>>>(src);
        knn_kernel<<<N / 8, 256>>>();
        agg_kernel<<<N / 4, 128>>>(src, convW, convb, bn_g, bn_b, bn_m, bn_v, l);
        src ^= 1;
    }

    heads_kernel<<<N / 32, 256>>>(src, outW1, outb1, outW2, outb2, outW3, outb3,
                                  spW1, spb1, spW2, spb2, spW3, spb3,
                                  (float*)d_out, out_size, N);
}